// round 8
// baseline (speedup 1.0000x reference)
#include <cuda_runtime.h>
#include <cuda_fp16.h>
#include <cstdint>

// Problem constants
#define NN 8192
#define DD 128
static constexpr float MARGIN = 1.0f;

// Tiling
static constexpr int BM = 128, BN = 128;
static constexpr int BKH = 64;                       // HMMA path K-chunk
static constexpr int BKF = 32;                       // FFMA path K-chunk
static constexpr int FSTRIDE = 132;                  // padded float row stride
static constexpr int THREADS = 256;
static constexpr int MAXP = 1 << 20;
static constexpr int NTILES = (NN / BM) * (NN / BN); // 4096
static constexpr int GRID = 296;                     // 148 HMMA + 148 FFMA
static constexpr int PAIR_BLOCKS = 512;
// smem: HMMA needs 2*128*64*2 = 32768; FFMA needs 2*32*132*4 = 33792
static constexpr int DYN_SMEM = 2 * BKF * FSTRIDE * 4;   // 33792

// ---------------------------------------------------------------------------
// Device globals
// ---------------------------------------------------------------------------
__device__ float g_V[NN];
__device__ float g_loss_sum;
__device__ int   g_pair_cnt;
__device__ int   g_done_blocks;
__device__ int   g_tile;
__device__ int   g_pi[MAXP];
__device__ int   g_pj[MAXP];
__device__ __align__(16) __half g_Ah[NN * DD];
__device__ __align__(16) __half g_Bh[NN * DD];

// ---------------------------------------------------------------------------
// PTX helpers
// ---------------------------------------------------------------------------
__device__ __forceinline__ void ldsm_x4(uint32_t& r0, uint32_t& r1, uint32_t& r2, uint32_t& r3,
                                        uint32_t saddr) {
    asm volatile("ldmatrix.sync.aligned.m8n8.x4.shared.b16 {%0,%1,%2,%3}, [%4];"
                 : "=r"(r0), "=r"(r1), "=r"(r2), "=r"(r3) : "r"(saddr));
}
__device__ __forceinline__ void mma_f16(float* d,
                                        uint32_t a0, uint32_t a1, uint32_t a2, uint32_t a3,
                                        uint32_t b0, uint32_t b1) {
    asm volatile(
        "mma.sync.aligned.m16n8k16.row.col.f32.f16.f16.f32 "
        "{%0,%1,%2,%3}, {%4,%5,%6,%7}, {%8,%9}, {%0,%1,%2,%3};"
        : "+f"(d[0]), "+f"(d[1]), "+f"(d[2]), "+f"(d[3])
        : "r"(a0), "r"(a1), "r"(a2), "r"(a3), "r"(b0), "r"(b1));
}
__device__ __forceinline__ uint32_t h2u(__half2 h) {
    return *reinterpret_cast<uint32_t*>(&h);
}
__device__ __forceinline__ unsigned long long pack_dup(float a) {
    unsigned long long u;
    uint32_t ai = __float_as_uint(a);
    asm("mov.b64 %0, {%1, %1};" : "=l"(u) : "r"(ai));
    return u;
}
__device__ __forceinline__ unsigned long long pack2(float lo, float hi) {
    unsigned long long u;
    asm("mov.b64 %0, {%1, %2};" : "=l"(u) : "r"(__float_as_uint(lo)), "r"(__float_as_uint(hi)));
    return u;
}
__device__ __forceinline__ void fma_x2(unsigned long long& d, unsigned long long a,
                                       unsigned long long b) {
    asm("fma.rn.f32x2 %0, %1, %2, %0;" : "+l"(d) : "l"(a), "l"(b));
}
__device__ __forceinline__ float2 unpack2(unsigned long long u) {
    float2 f;
    uint32_t lo, hi;
    asm("mov.b64 {%0, %1}, %2;" : "=r"(lo), "=r"(hi) : "l"(u));
    f.x = __uint_as_float(lo);
    f.y = __uint_as_float(hi);
    return f;
}

// ---------------------------------------------------------------------------
// Kernel 0: f32 -> f16 conversion + accumulator/queue zeroing (every replay)
// ---------------------------------------------------------------------------
__global__ void k_convert(const float* __restrict__ A, const float* __restrict__ B) {
    int t = blockIdx.x * blockDim.x + threadIdx.x;     // 0 .. NN*DD/4-1
    float4 va = ((const float4*)A)[t];
    float4 vb = ((const float4*)B)[t];
    uint2 ua = make_uint2(h2u(__floats2half2_rn(va.x, va.y)),
                          h2u(__floats2half2_rn(va.z, va.w)));
    uint2 ub = make_uint2(h2u(__floats2half2_rn(vb.x, vb.y)),
                          h2u(__floats2half2_rn(vb.z, vb.w)));
    ((uint2*)g_Ah)[t] = ua;
    ((uint2*)g_Bh)[t] = ub;
    if (t < NN) g_V[t] = 0.0f;
    if (t == 0) { g_loss_sum = 0.0f; g_pair_cnt = 0; g_done_blocks = 0; g_tile = 0; }
}

// ---------------------------------------------------------------------------
// Kernel 1: persistent heterogeneous GEMM over an atomic tile queue.
//   CTAs 0-147:   fp16 HMMA tiles (tensor pipe)    -- proven R4 core
//   CTAs 148-295: f32 FFMA2 (fma.rn.f32x2) tiles (fma pipe), exact f32
// Epilogue (both): V[i] += sum_{labels differ} exp(MARGIN+S); capture pos (i,j).
// ---------------------------------------------------------------------------
__global__ __launch_bounds__(THREADS, 2)
void k_gemm(const float* __restrict__ A, const float* __restrict__ B,
            const int* __restrict__ labels) {
    extern __shared__ __align__(16) char smem[];
    __shared__ float sV[BM];
    __shared__ int   sLi[BM];
    __shared__ int   sLj[BN];
    __shared__ int   s_tile;

    const int tid  = threadIdx.x;
    const int wid  = tid >> 5;
    const int lane = tid & 31;
    const bool is_ffma = (blockIdx.x >= 148);

    // ---- HMMA constants ----
    const int g  = lane >> 2;
    const int l4 = lane & 3;
    const int wm = wid >> 2;
    const int wn = wid & 3;
    const uint32_t as_base = (uint32_t)__cvta_generic_to_shared(smem);
    const uint32_t bs_base = as_base + BM * BKH * 2;
    const int q  = lane >> 3;
    const int rr = lane & 7;
    uint32_t a_rowbase[4]; int a_sw[4];
    const int a_cq = q >> 1;
#pragma unroll
    for (int mi = 0; mi < 4; ++mi) {
        int row = wm * 64 + mi * 16 + (q & 1) * 8 + rr;
        a_rowbase[mi] = as_base + row * (BKH * 2);
        a_sw[mi] = row & 7;
    }
    uint32_t b_rowbase[2]; int b_sw[2];
    const int b_cq = q & 1;
#pragma unroll
    for (int p = 0; p < 2; ++p) {
        int n = wn * 32 + p * 16 + (q >> 1) * 8 + rr;
        b_rowbase[p] = bs_base + n * (BKH * 2);
        b_sw[p] = n & 7;
    }

    // ---- FFMA constants ----
    const int tx = tid & 15;   // column group (8 cols)
    const int ty = tid >> 4;   // row group (8 rows)
    float* Af = (float*)smem;                       // [BKF][FSTRIDE]
    float* Bf = (float*)(smem + BKF * FSTRIDE * 4); // [BKF][FSTRIDE]
    const int kq = tid & 7;    // float4 group within BKF=32
    const int r0 = tid >> 3;   // 0..31

    for (;;) {
        if (tid == 0) s_tile = atomicAdd(&g_tile, 1);
        __syncthreads();
        const int t = s_tile;
        if (t >= NTILES) break;
        const int bi = (t >> 6) * BM;
        const int bj = (t & 63) * BN;

        if (tid < BM) { sV[tid] = 0.0f; sLi[tid] = labels[bi + tid]; }
        else if (tid < BM + BN) { sLj[tid - BM] = labels[bj + (tid - BM)]; }

        if (!is_ffma) {
            // ====================== HMMA fp16 path (R4 core) ======================
            __half* As = (__half*)smem;
            __half* Bs = (__half*)(smem + BM * BKH * 2);
            float sacc[4][4][4];
#pragma unroll
            for (int mi = 0; mi < 4; ++mi)
#pragma unroll
                for (int ni = 0; ni < 4; ++ni)
#pragma unroll
                    for (int e = 0; e < 4; ++e) sacc[mi][ni][e] = 0.0f;

            for (int c = 0; c < DD / BKH; ++c) {
                const int k0 = c * BKH;
                if (c > 0) __syncthreads();
#pragma unroll
                for (int tt = 0; tt < 4; ++tt) {
                    int idx = tid + tt * THREADS;
                    int row = idx >> 3;
                    int cc  = idx & 7;
                    int sw  = cc ^ (row & 7);
                    *(uint4*)&As[row * BKH + sw * 8] =
                        *(const uint4*)&g_Ah[(size_t)(bi + row) * DD + k0 + cc * 8];
                    *(uint4*)&Bs[row * BKH + sw * 8] =
                        *(const uint4*)&g_Bh[(size_t)(bj + row) * DD + k0 + cc * 8];
                }
                __syncthreads();

#pragma unroll
                for (int kk = 0; kk < BKH / 16; ++kk) {
                    const int cb = kk * 2;
                    uint32_t af[4][4];
#pragma unroll
                    for (int mi = 0; mi < 4; ++mi)
                        ldsm_x4(af[mi][0], af[mi][1], af[mi][2], af[mi][3],
                                a_rowbase[mi] + (((cb + a_cq) ^ a_sw[mi]) << 4));
                    uint32_t bf[2][4];
#pragma unroll
                    for (int p = 0; p < 2; ++p)
                        ldsm_x4(bf[p][0], bf[p][1], bf[p][2], bf[p][3],
                                b_rowbase[p] + (((cb + b_cq) ^ b_sw[p]) << 4));
#pragma unroll
                    for (int mi = 0; mi < 4; ++mi) {
#pragma unroll
                        for (int p = 0; p < 2; ++p) {
                            mma_f16(sacc[mi][2 * p + 0], af[mi][0], af[mi][1], af[mi][2], af[mi][3],
                                    bf[p][0], bf[p][1]);
                            mma_f16(sacc[mi][2 * p + 1], af[mi][0], af[mi][1], af[mi][2], af[mi][3],
                                    bf[p][2], bf[p][3]);
                        }
                    }
                }
            }
            __syncthreads();

            // ---- HMMA epilogue ----
#pragma unroll
            for (int mi = 0; mi < 4; ++mi) {
                const int row0 = wm * 64 + mi * 16 + g;
                const int row1 = row0 + 8;
                const int li0 = sLi[row0], li1 = sLi[row1];
                float v0 = 0.0f, v1 = 0.0f;
#pragma unroll
                for (int ni = 0; ni < 4; ++ni) {
                    const int colb = wn * 32 + ni * 8 + 2 * l4;
                    const int ljA = sLj[colb], ljB = sLj[colb + 1];
#pragma unroll
                    for (int e = 0; e < 4; ++e) {
                        const float s = sacc[mi][ni][e];
                        const int li  = (e & 2) ? li1 : li0;
                        const int lj  = (e & 1) ? ljB : ljA;
                        if (li != lj) {
                            float ev = __expf(MARGIN + s);
                            if (e & 2) v1 += ev; else v0 += ev;
                        } else {
                            int gi = bi + ((e & 2) ? row1 : row0);
                            int gj = bj + colb + (e & 1);
                            if (gi != gj) {
                                int x = atomicAdd(&g_pair_cnt, 1);
                                if (x < MAXP) { g_pi[x] = gi; g_pj[x] = gj; }
                            }
                        }
                    }
                }
                v0 += __shfl_xor_sync(0xffffffffu, v0, 1);
                v0 += __shfl_xor_sync(0xffffffffu, v0, 2);
                v1 += __shfl_xor_sync(0xffffffffu, v1, 1);
                v1 += __shfl_xor_sync(0xffffffffu, v1, 2);
                if (l4 == 0) {
                    atomicAdd(&sV[row0], v0);
                    atomicAdd(&sV[row1], v1);
                }
            }
        } else {
            // ====================== FFMA2 f32 path ======================
            unsigned long long acc2[8][4];
#pragma unroll
            for (int r = 0; r < 8; ++r)
#pragma unroll
                for (int p = 0; p < 4; ++p) acc2[r][p] = 0ull;

            for (int c = 0; c < DD / BKF; ++c) {
                const int k0 = c * BKF;
                if (c > 0) __syncthreads();
#pragma unroll
                for (int rrr = 0; rrr < BM; rrr += 32) {
                    int row = r0 + rrr;
                    float4 va = *(const float4*)&A[(size_t)(bi + row) * DD + k0 + kq * 4];
                    float4 vb = *(const float4*)&B[(size_t)(bj + row) * DD + k0 + kq * 4];
                    Af[(kq * 4 + 0) * FSTRIDE + row] = va.x;
                    Af[(kq * 4 + 1) * FSTRIDE + row] = va.y;
                    Af[(kq * 4 + 2) * FSTRIDE + row] = va.z;
                    Af[(kq * 4 + 3) * FSTRIDE + row] = va.w;
                    Bf[(kq * 4 + 0) * FSTRIDE + row] = vb.x;
                    Bf[(kq * 4 + 1) * FSTRIDE + row] = vb.y;
                    Bf[(kq * 4 + 2) * FSTRIDE + row] = vb.z;
                    Bf[(kq * 4 + 3) * FSTRIDE + row] = vb.w;
                }
                __syncthreads();

#pragma unroll 8
                for (int k = 0; k < BKF; ++k) {
                    float4 a01 = *(const float4*)&Af[k * FSTRIDE + ty * 8];
                    float4 a45 = *(const float4*)&Af[k * FSTRIDE + ty * 8 + 4];
                    float4 b01 = *(const float4*)&Bf[k * FSTRIDE + tx * 8];
                    float4 b45 = *(const float4*)&Bf[k * FSTRIDE + tx * 8 + 4];
                    unsigned long long bd[4];
                    bd[0] = pack2(b01.x, b01.y);
                    bd[1] = pack2(b01.z, b01.w);
                    bd[2] = pack2(b45.x, b45.y);
                    bd[3] = pack2(b45.z, b45.w);
                    unsigned long long ad[8];
                    ad[0] = pack_dup(a01.x); ad[1] = pack_dup(a01.y);
                    ad[2] = pack_dup(a01.z); ad[3] = pack_dup(a01.w);
                    ad[4] = pack_dup(a45.x); ad[5] = pack_dup(a45.y);
                    ad[6] = pack_dup(a45.z); ad[7] = pack_dup(a45.w);
#pragma unroll
                    for (int r = 0; r < 8; ++r)
#pragma unroll
                        for (int p = 0; p < 4; ++p)
                            fma_x2(acc2[r][p], ad[r], bd[p]);
                }
            }
            __syncthreads();

            // ---- FFMA epilogue ----
#pragma unroll
            for (int r = 0; r < 8; ++r) {
                const int row = ty * 8 + r;
                const int li  = sLi[row];
                const int gi  = bi + row;
                float vsum = 0.0f;
#pragma unroll
                for (int p = 0; p < 4; ++p) {
                    float2 s2 = unpack2(acc2[r][p]);
                    int col0 = tx * 8 + 2 * p;
                    int lj0 = sLj[col0], lj1 = sLj[col0 + 1];
                    if (li != lj0) vsum += __expf(MARGIN + s2.x);
                    else { int gj = bj + col0;
                           if (gi != gj) { int x = atomicAdd(&g_pair_cnt, 1);
                                           if (x < MAXP) { g_pi[x] = gi; g_pj[x] = gj; } } }
                    if (li != lj1) vsum += __expf(MARGIN + s2.y);
                    else { int gj = bj + col0 + 1;
                           if (gi != gj) { int x = atomicAdd(&g_pair_cnt, 1);
                                           if (x < MAXP) { g_pi[x] = gi; g_pj[x] = gj; } } }
                }
                vsum += __shfl_xor_sync(0xffffffffu, vsum, 1);
                vsum += __shfl_xor_sync(0xffffffffu, vsum, 2);
                vsum += __shfl_xor_sync(0xffffffffu, vsum, 4);
                vsum += __shfl_xor_sync(0xffffffffu, vsum, 8);
                if ((lane & 15) == 0) atomicAdd(&sV[row], vsum);
            }
        }

        __syncthreads();
        if (tid < BM) atomicAdd(&g_V[bi + tid], sV[tid]);
    }
}

// ---------------------------------------------------------------------------
// Kernel 2: hinge over positive pairs (exact f32 S_ij recompute) + final scalar
// ---------------------------------------------------------------------------
__global__ void k_pairs(const float* __restrict__ A, const float* __restrict__ B,
                        float* __restrict__ out) {
    int n = g_pair_cnt;
    if (n > MAXP) n = MAXP;
    const int lane   = threadIdx.x & 31;
    const int warp   = (blockIdx.x * blockDim.x + threadIdx.x) >> 5;
    const int nwarps = (gridDim.x * blockDim.x) >> 5;

    float local = 0.0f;
    for (int p = warp; p < n; p += nwarps) {
        int i = g_pi[p], j = g_pj[p];
        float4 va = ((const float4*)A)[i * (DD / 4) + lane];
        float4 vb = ((const float4*)B)[j * (DD / 4) + lane];
        float s = va.x * vb.x + va.y * vb.y + va.z * vb.z + va.w * vb.w;
        s += __shfl_xor_sync(0xffffffffu, s, 16);
        s += __shfl_xor_sync(0xffffffffu, s, 8);
        s += __shfl_xor_sync(0xffffffffu, s, 4);
        s += __shfl_xor_sync(0xffffffffu, s, 2);
        s += __shfl_xor_sync(0xffffffffu, s, 1);
        if (lane == 0) {
            float v = g_V[i] + g_V[j];
            float h = fmaxf(logf(v) - s, 0.0f);
            local += h * h;
        }
    }
    local += __shfl_xor_sync(0xffffffffu, local, 16);
    local += __shfl_xor_sync(0xffffffffu, local, 8);
    local += __shfl_xor_sync(0xffffffffu, local, 4);
    local += __shfl_xor_sync(0xffffffffu, local, 2);
    local += __shfl_xor_sync(0xffffffffu, local, 1);

    __shared__ float wsum[8];
    int w = threadIdx.x >> 5;
    if (lane == 0) wsum[w] = local;
    __syncthreads();
    if (threadIdx.x == 0) {
        float s = 0.0f;
        int nw = (blockDim.x + 31) >> 5;
        for (int i = 0; i < nw; ++i) s += wsum[i];
        atomicAdd(&g_loss_sum, s);
        __threadfence();
        int done = atomicAdd(&g_done_blocks, 1);
        if (done == gridDim.x - 1) {
            out[0] = g_loss_sum / (2.0f * (float)g_pair_cnt);
        }
    }
}

// ---------------------------------------------------------------------------
extern "C" void kernel_launch(void* const* d_in, const int* in_sizes, int n_in,
                              void* d_out, int out_size) {
    const float* a      = (const float*)d_in[0];
    const float* b      = (const float*)d_in[1];
    const int*   labels = (const int*)d_in[2];
    float*       out    = (float*)d_out;

    k_convert<<<(NN * DD / 4) / 256, 256>>>(a, b);
    k_gemm<<<GRID, THREADS, DYN_SMEM>>>(a, b, labels);
    k_pairs<<<PAIR_BLOCKS, 256>>>(a, b, out);
}

// round 9
// speedup vs baseline: 1.8017x; 1.8017x over previous
#include <cuda_runtime.h>
#include <cuda_fp16.h>
#include <cstdint>

// Problem constants
#define NN 8192
#define DD 128
static constexpr float MARGIN = 1.0f;

// Tiling: 128x128 CTA tile, full K=128 resident (f16 = 32KB per matrix)
static constexpr int BM = 128, BN = 128;
static constexpr int THREADS = 256;           // 8 warps: 2 (m) x 4 (n)
static constexpr int MAXP = 1 << 20;
static constexpr int PAIR_BLOCKS = 512;

// ---------------------------------------------------------------------------
// Device globals
// ---------------------------------------------------------------------------
__device__ float g_V[NN];
__device__ float g_loss_sum;
__device__ int   g_pair_cnt;
__device__ int   g_done_blocks;
__device__ int   g_pi[MAXP];
__device__ int   g_pj[MAXP];
__device__ __align__(16) __half g_Ah[NN * DD];
__device__ __align__(16) __half g_Bh[NN * DD];

// ---------------------------------------------------------------------------
// PTX helpers
// ---------------------------------------------------------------------------
__device__ __forceinline__ void ldsm_x4(uint32_t& r0, uint32_t& r1, uint32_t& r2, uint32_t& r3,
                                        uint32_t saddr) {
    asm volatile("ldmatrix.sync.aligned.m8n8.x4.shared.b16 {%0,%1,%2,%3}, [%4];"
                 : "=r"(r0), "=r"(r1), "=r"(r2), "=r"(r3) : "r"(saddr));
}
__device__ __forceinline__ void mma_f16(float* d,
                                        uint32_t a0, uint32_t a1, uint32_t a2, uint32_t a3,
                                        uint32_t b0, uint32_t b1) {
    asm volatile(
        "mma.sync.aligned.m16n8k16.row.col.f32.f16.f16.f32 "
        "{%0,%1,%2,%3}, {%4,%5,%6,%7}, {%8,%9}, {%0,%1,%2,%3};"
        : "+f"(d[0]), "+f"(d[1]), "+f"(d[2]), "+f"(d[3])
        : "r"(a0), "r"(a1), "r"(a2), "r"(a3), "r"(b0), "r"(b1));
}
__device__ __forceinline__ uint32_t h2u(__half2 h) {
    return *reinterpret_cast<uint32_t*>(&h);
}

// ---------------------------------------------------------------------------
// Kernel 0: f32 -> f16 conversion + accumulator zeroing (every replay)
// ---------------------------------------------------------------------------
__global__ void k_convert(const float* __restrict__ A, const float* __restrict__ B) {
    int t = blockIdx.x * blockDim.x + threadIdx.x;     // 0 .. NN*DD/4-1
    float4 va = ((const float4*)A)[t];
    float4 vb = ((const float4*)B)[t];
    uint2 ua = make_uint2(h2u(__floats2half2_rn(va.x, va.y)),
                          h2u(__floats2half2_rn(va.z, va.w)));
    uint2 ub = make_uint2(h2u(__floats2half2_rn(vb.x, vb.y)),
                          h2u(__floats2half2_rn(vb.z, vb.w)));
    ((uint2*)g_Ah)[t] = ua;
    ((uint2*)g_Bh)[t] = ub;
    if (t < NN) g_V[t] = 0.0f;
    if (t == 0) { g_loss_sum = 0.0f; g_pair_cnt = 0; g_done_blocks = 0; }
}

// ---------------------------------------------------------------------------
// Kernel 1: fp16 mma.sync (f32 accum) GEMM S = A * B^T, full-K tiles,
// fused epilogue: V[i] += sum_{labels differ} exp(MARGIN + S_ij);
// capture positive (i,j) pairs for exact recompute.
// Smem rows = 256 B = 16 chunks of 16 B; swizzle on low 3 chunk bits ^ (row&7).
// ---------------------------------------------------------------------------
__global__ __launch_bounds__(THREADS, 2)
void k_gemm(const int* __restrict__ labels) {
    __shared__ __align__(16) __half As[BM * DD];   // 32 KB
    __shared__ __align__(16) __half Bs[BN * DD];   // 32 KB
    __shared__ float sV[BM];
    __shared__ int   sLi[BM];
    __shared__ int   sLj[BN];

    const int tid  = threadIdx.x;
    const int wid  = tid >> 5;
    const int lane = tid & 31;
    const int g    = lane >> 2;
    const int l4   = lane & 3;
    const int wm   = wid >> 2;
    const int wn   = wid & 3;
    const int bi   = blockIdx.y * BM;
    const int bj   = blockIdx.x * BN;

    if (tid < BM) { sV[tid] = 0.0f; sLi[tid] = labels[bi + tid]; }
    else if (tid < BM + BN) { sLj[tid - BM] = labels[bj + (tid - BM)]; }

    // Load full K=128 tiles: 2048 uint4 per matrix, 8 per thread.
#pragma unroll
    for (int t = 0; t < 8; ++t) {
        int idx = tid + t * THREADS;           // 0..2047
        int row = idx >> 4;                    // 0..127
        int cc  = idx & 15;                    // 16B chunk 0..15
        int sw  = (cc & 8) | ((cc & 7) ^ (row & 7));
        *(uint4*)&As[row * DD + sw * 8] =
            *(const uint4*)&g_Ah[(size_t)(bi + row) * DD + cc * 8];
        *(uint4*)&Bs[row * DD + sw * 8] =
            *(const uint4*)&g_Bh[(size_t)(bj + row) * DD + cc * 8];
    }
    __syncthreads();

    const uint32_t as_base = (uint32_t)__cvta_generic_to_shared(As);
    const uint32_t bs_base = (uint32_t)__cvta_generic_to_shared(Bs);

    // ldmatrix lane->address precompute
    const int q  = lane >> 3;     // matrix index 0..3
    const int rr = lane & 7;      // row within matrix
    uint32_t a_rowbase[4];
    int      a_sw[4];
    const int a_cq = q >> 1;      // A: q2,q3 are the +16B k-half
#pragma unroll
    for (int mi = 0; mi < 4; ++mi) {
        int row = wm * 64 + mi * 16 + (q & 1) * 8 + rr;
        a_rowbase[mi] = as_base + row * (DD * 2);
        a_sw[mi] = row & 7;
    }
    uint32_t b_rowbase[2];
    int      b_sw[2];
    const int b_cq = q & 1;       // B: q1,q3 are the +16B k-half
#pragma unroll
    for (int p = 0; p < 2; ++p) {
        int n = wn * 32 + p * 16 + (q >> 1) * 8 + rr;
        b_rowbase[p] = bs_base + n * (DD * 2);
        b_sw[p] = n & 7;
    }

    float acc[4][4][4];
#pragma unroll
    for (int mi = 0; mi < 4; ++mi)
#pragma unroll
        for (int ni = 0; ni < 4; ++ni)
#pragma unroll
            for (int e = 0; e < 4; ++e) acc[mi][ni][e] = 0.0f;

#pragma unroll
    for (int kk = 0; kk < DD / 16; ++kk) {     // 8 k16 steps
        const int cb = kk * 2;                 // base 16B chunk (0..14)
        uint32_t af[4][4];
#pragma unroll
        for (int mi = 0; mi < 4; ++mi) {
            int c = cb + a_cq;
            int swc = (c & 8) | ((c & 7) ^ a_sw[mi]);
            ldsm_x4(af[mi][0], af[mi][1], af[mi][2], af[mi][3],
                    a_rowbase[mi] + (swc << 4));
        }
        uint32_t bf[2][4];
#pragma unroll
        for (int p = 0; p < 2; ++p) {
            int c = cb + b_cq;
            int swc = (c & 8) | ((c & 7) ^ b_sw[p]);
            ldsm_x4(bf[p][0], bf[p][1], bf[p][2], bf[p][3],
                    b_rowbase[p] + (swc << 4));
        }
#pragma unroll
        for (int mi = 0; mi < 4; ++mi) {
#pragma unroll
            for (int p = 0; p < 2; ++p) {
                mma_f16(acc[mi][2 * p + 0], af[mi][0], af[mi][1], af[mi][2], af[mi][3],
                        bf[p][0], bf[p][1]);
                mma_f16(acc[mi][2 * p + 1], af[mi][0], af[mi][1], af[mi][2], af[mi][3],
                        bf[p][2], bf[p][3]);
            }
        }
    }
    __syncthreads();

    // ---------------- Epilogue ----------------
#pragma unroll
    for (int mi = 0; mi < 4; ++mi) {
        const int row0 = wm * 64 + mi * 16 + g;
        const int row1 = row0 + 8;
        const int li0 = sLi[row0], li1 = sLi[row1];
        float v0 = 0.0f, v1 = 0.0f;
#pragma unroll
        for (int ni = 0; ni < 4; ++ni) {
            const int colb = wn * 32 + ni * 8 + 2 * l4;
            const int ljA = sLj[colb], ljB = sLj[colb + 1];
#pragma unroll
            for (int e = 0; e < 4; ++e) {
                const float s = acc[mi][ni][e];
                const int li  = (e & 2) ? li1 : li0;
                const int lj  = (e & 1) ? ljB : ljA;
                if (li != lj) {
                    float ev = __expf(MARGIN + s);
                    if (e & 2) v1 += ev; else v0 += ev;
                } else {
                    int gi = bi + ((e & 2) ? row1 : row0);
                    int gj = bj + colb + (e & 1);
                    if (gi != gj) {
                        int x = atomicAdd(&g_pair_cnt, 1);
                        if (x < MAXP) { g_pi[x] = gi; g_pj[x] = gj; }
                    }
                }
            }
        }
        v0 += __shfl_xor_sync(0xffffffffu, v0, 1);
        v0 += __shfl_xor_sync(0xffffffffu, v0, 2);
        v1 += __shfl_xor_sync(0xffffffffu, v1, 1);
        v1 += __shfl_xor_sync(0xffffffffu, v1, 2);
        if (l4 == 0) {
            atomicAdd(&sV[row0], v0);
            atomicAdd(&sV[row1], v1);
        }
    }
    __syncthreads();
    if (tid < BM) atomicAdd(&g_V[bi + tid], sV[tid]);
}

// ---------------------------------------------------------------------------
// Kernel 2: hinge over positive pairs (exact f32 S_ij recompute) + final scalar
// ---------------------------------------------------------------------------
__global__ void k_pairs(const float* __restrict__ A, const float* __restrict__ B,
                        float* __restrict__ out) {
    int n = g_pair_cnt;
    if (n > MAXP) n = MAXP;
    const int lane   = threadIdx.x & 31;
    const int warp   = (blockIdx.x * blockDim.x + threadIdx.x) >> 5;
    const int nwarps = (gridDim.x * blockDim.x) >> 5;

    float local = 0.0f;
    for (int p = warp; p < n; p += nwarps) {
        int i = g_pi[p], j = g_pj[p];
        float4 va = ((const float4*)A)[i * (DD / 4) + lane];
        float4 vb = ((const float4*)B)[j * (DD / 4) + lane];
        float s = va.x * vb.x + va.y * vb.y + va.z * vb.z + va.w * vb.w;
        s += __shfl_xor_sync(0xffffffffu, s, 16);
        s += __shfl_xor_sync(0xffffffffu, s, 8);
        s += __shfl_xor_sync(0xffffffffu, s, 4);
        s += __shfl_xor_sync(0xffffffffu, s, 2);
        s += __shfl_xor_sync(0xffffffffu, s, 1);
        if (lane == 0) {
            float v = g_V[i] + g_V[j];
            float h = fmaxf(logf(v) - s, 0.0f);
            local += h * h;
        }
    }
    local += __shfl_xor_sync(0xffffffffu, local, 16);
    local += __shfl_xor_sync(0xffffffffu, local, 8);
    local += __shfl_xor_sync(0xffffffffu, local, 4);
    local += __shfl_xor_sync(0xffffffffu, local, 2);
    local += __shfl_xor_sync(0xffffffffu, local, 1);

    __shared__ float wsum[8];
    int w = threadIdx.x >> 5;
    if (lane == 0) wsum[w] = local;
    __syncthreads();
    if (threadIdx.x == 0) {
        float s = 0.0f;
        int nw = (blockDim.x + 31) >> 5;
        for (int i = 0; i < nw; ++i) s += wsum[i];
        atomicAdd(&g_loss_sum, s);
        __threadfence();
        int done = atomicAdd(&g_done_blocks, 1);
        if (done == gridDim.x - 1) {
            out[0] = g_loss_sum / (2.0f * (float)g_pair_cnt);
        }
    }
}

// ---------------------------------------------------------------------------
extern "C" void kernel_launch(void* const* d_in, const int* in_sizes, int n_in,
                              void* d_out, int out_size) {
    const float* a      = (const float*)d_in[0];
    const float* b      = (const float*)d_in[1];
    const int*   labels = (const int*)d_in[2];
    float*       out    = (float*)d_out;

    k_convert<<<(NN * DD / 4) / 256, 256>>>(a, b);

    dim3 grid(NN / BN, NN / BM);   // 64 x 64
    k_gemm<<<grid, THREADS>>>(labels);

    k_pairs<<<PAIR_BLOCKS, 256>>>(a, b, out);
}